// round 1
// baseline (speedup 1.0000x reference)
#include <cuda_runtime.h>
#include <math.h>

// Problem constants (fixed by setup_inputs: N=100000, D=64, K=2, E=1600000)
#define DD    64
#define N_MAX 100000
#define K_MAX 2
#define EPSV  1e-8f

// Scratch (static __device__ arrays — allocation-free per harness rules)
// g_X[m]: m = k        -> alpha[k] * (d_out*H) @ theta_out[k]   (source for A_k scatter)
//         m = K_MAX+k  -> alpha[k] * (d_in *H) @ theta_in[k]    (source for A_k^T scatter)
__device__ float g_X[2 * K_MAX][(size_t)N_MAX * DD];
__device__ float g_Sum[(size_t)N_MAX * DD];
__device__ float g_alpha[K_MAX];

// ---------------------------------------------------------------------------
// 1) softmax over hop_attention (K tiny)
// ---------------------------------------------------------------------------
__global__ void alpha_kernel(const float* __restrict__ hop, int K) {
    if (threadIdx.x == 0 && blockIdx.x == 0) {
        float mx = -1e30f;
        for (int k = 0; k < K; k++) mx = fmaxf(mx, hop[k]);
        float e[K_MAX];
        float s = 0.f;
        for (int k = 0; k < K; k++) { e[k] = __expf(hop[k] - mx); s += e[k]; }
        float inv = 1.f / s;
        for (int k = 0; k < K; k++) g_alpha[k] = e[k] * inv;
    }
}

// ---------------------------------------------------------------------------
// 2) X generation: for each node row, compute all 4 projected rows at once.
//    Also zeroes g_Sum.
//    Block = 256 threads; 32 rows per block-iteration; each warp computes 4
//    rows with register-blocked accumulation; theta (4 matrices, m-interleaved
//    as float4, pre-scaled by alpha[k]) lives in shared memory.
// ---------------------------------------------------------------------------
__global__ void xgen_kernel(const float* __restrict__ H,
                            const float* __restrict__ out_deg,
                            const float* __restrict__ in_deg,
                            const float* __restrict__ theta_out,
                            const float* __restrict__ theta_in,
                            int N, int K) {
    extern __shared__ float smem[];
    float4* s_theta = (float4*)smem;               // [64*64] float4 (m-interleaved) = 64KB
    float*  s_ho    = smem + DD * DD * 4;          // [32*64] d_out-scaled rows = 8KB
    float*  s_hi    = s_ho + 32 * DD;              // [32*64] d_in-scaled rows  = 8KB

    const int tid  = threadIdx.x;
    const int warp = tid >> 5;
    const int lane = tid & 31;

    // Stage theta: slot .x = out k0, .y = out k1, .z = in k0, .w = in k1
    {
        float a0 = g_alpha[0];
        float a1 = (K > 1) ? g_alpha[1] : 0.f;
        for (int idx = tid; idx < DD * DD; idx += blockDim.x) {
            float4 t;
            t.x = a0 * theta_out[idx];
            t.y = (K > 1) ? a1 * theta_out[DD * DD + idx] : 0.f;
            t.z = a0 * theta_in[idx];
            t.w = (K > 1) ? a1 * theta_in[DD * DD + idx] : 0.f;
            s_theta[idx] = t;
        }
    }

    for (int base = blockIdx.x * 32; base < N; base += gridDim.x * 32) {
        __syncthreads();   // protects s_theta (iter 0) and s_ho/s_hi reuse
        const int nrows = min(32, N - base);

        // Stage 32 rows, pre-scaled by max(degree, eps)
        for (int idx = tid; idx < nrows * DD; idx += blockDim.x) {
            int rl = idx >> 6;
            int j  = idx & 63;
            int g  = base + rl;
            float h   = H[(size_t)g * DD + j];
            float dod = fmaxf(out_deg[g], EPSV);
            float did = fmaxf(in_deg[g], EPSV);
            s_ho[idx] = h * dod;
            s_hi[idx] = h * did;
        }
        // Zero accumulator buffer for these rows
        for (int idx = tid; idx < nrows * DD; idx += blockDim.x)
            g_Sum[(size_t)base * DD + idx] = 0.f;
        __syncthreads();

        const int r0 = warp * 4;   // local row base for this warp
        if (base + r0 < N) {
            float4 aLo[4], aHi[4];
            #pragma unroll
            for (int r = 0; r < 4; r++) {
                aLo[r] = make_float4(0.f, 0.f, 0.f, 0.f);
                aHi[r] = make_float4(0.f, 0.f, 0.f, 0.f);
            }
            #pragma unroll 16
            for (int j = 0; j < DD; j++) {
                float4 tLo = s_theta[j * DD + lane];
                float4 tHi = s_theta[j * DD + lane + 32];
                #pragma unroll
                for (int r = 0; r < 4; r++) {
                    float a = s_ho[(r0 + r) * DD + j];   // broadcast
                    float b = s_hi[(r0 + r) * DD + j];   // broadcast
                    aLo[r].x += a * tLo.x;  aLo[r].y += a * tLo.y;
                    aLo[r].z += b * tLo.z;  aLo[r].w += b * tLo.w;
                    aHi[r].x += a * tHi.x;  aHi[r].y += a * tHi.y;
                    aHi[r].z += b * tHi.z;  aHi[r].w += b * tHi.w;
                }
            }
            #pragma unroll
            for (int r = 0; r < 4; r++) {
                int grow = base + r0 + r;
                if (grow < N) {
                    size_t o = (size_t)grow * DD;
                    g_X[0][o + lane]      = aLo[r].x;
                    g_X[1][o + lane]      = aLo[r].y;
                    g_X[K_MAX + 0][o + lane]      = aLo[r].z;
                    g_X[K_MAX + 1][o + lane]      = aLo[r].w;
                    g_X[0][o + 32 + lane] = aHi[r].x;
                    g_X[1][o + 32 + lane] = aHi[r].y;
                    g_X[K_MAX + 0][o + 32 + lane] = aHi[r].z;
                    g_X[K_MAX + 1][o + 32 + lane] = aHi[r].w;
                }
            }
        }
    }
}

// ---------------------------------------------------------------------------
// 3) Edge scatter for hop k. 16 threads per edge; each thread moves a float4.
//    Sum[row] += v * Xout[col]   (t_out)
//    Sum[col] += v * Xin[row]    (t_in, transpose direction)
//    Vector no-return reductions (red.global.add.v4.f32) -> 4x fewer atomic ops.
// ---------------------------------------------------------------------------
__global__ void scatter_kernel(const int* __restrict__ rows,
                               const int* __restrict__ cols,
                               const float* __restrict__ vals,
                               int k, int E) {
    int t = blockIdx.x * blockDim.x + threadIdx.x;
    int g = t >> 4;        // edge index
    int l = t & 15;        // quad index within the 64-float row
    if (g >= E) return;

    int   r = __ldg(rows + g);
    int   c = __ldg(cols + g);
    float v = __ldg(vals + g);

    const float* Xout = g_X[k];
    const float* Xin  = g_X[K_MAX + k];

    float4 xo = __ldg((const float4*)(Xout + (size_t)c * DD) + l);
    float4 xi = __ldg((const float4*)(Xin  + (size_t)r * DD) + l);

    float* po = g_Sum + (size_t)r * DD + l * 4;
    float* pi = g_Sum + (size_t)c * DD + l * 4;

    asm volatile("red.global.add.v4.f32 [%0], {%1,%2,%3,%4};"
                 :: "l"(po), "f"(v * xo.x), "f"(v * xo.y), "f"(v * xo.z), "f"(v * xo.w)
                 : "memory");
    asm volatile("red.global.add.v4.f32 [%0], {%1,%2,%3,%4};"
                 :: "l"(pi), "f"(v * xi.x), "f"(v * xi.y), "f"(v * xi.z), "f"(v * xi.w)
                 : "memory");
}

// ---------------------------------------------------------------------------
// 4) Epilogue: out = sigmoid(Sum @ Theta) + H
// ---------------------------------------------------------------------------
__global__ void final_kernel(const float* __restrict__ H,
                             const float* __restrict__ Theta,
                             float* __restrict__ out, int N) {
    __shared__ float s_th[DD * DD];   // 16KB
    __shared__ float s_r[32 * DD];    // 8KB

    const int tid  = threadIdx.x;
    const int warp = tid >> 5;
    const int lane = tid & 31;

    for (int idx = tid; idx < DD * DD; idx += blockDim.x)
        s_th[idx] = Theta[idx];

    for (int base = blockIdx.x * 32; base < N; base += gridDim.x * 32) {
        __syncthreads();
        const int nrows = min(32, N - base);
        for (int idx = tid; idx < nrows * DD; idx += blockDim.x)
            s_r[idx] = g_Sum[(size_t)base * DD + idx];
        __syncthreads();

        const int r0 = warp * 4;
        if (base + r0 < N) {
            float aL[4] = {0.f, 0.f, 0.f, 0.f};
            float aH[4] = {0.f, 0.f, 0.f, 0.f};
            #pragma unroll 16
            for (int j = 0; j < DD; j++) {
                float tL = s_th[j * DD + lane];
                float tH = s_th[j * DD + lane + 32];
                #pragma unroll
                for (int r = 0; r < 4; r++) {
                    float s = s_r[(r0 + r) * DD + j];   // broadcast
                    aL[r] += s * tL;
                    aH[r] += s * tH;
                }
            }
            #pragma unroll
            for (int r = 0; r < 4; r++) {
                int grow = base + r0 + r;
                if (grow < N) {
                    size_t o = (size_t)grow * DD;
                    out[o + lane]      = 1.f / (1.f + __expf(-aL[r])) + H[o + lane];
                    out[o + 32 + lane] = 1.f / (1.f + __expf(-aH[r])) + H[o + 32 + lane];
                }
            }
        }
    }
}

// ---------------------------------------------------------------------------
// Launch. Input order per metadata:
//   0:H[N,64] 1:edge_vals[K,E] 2:out_degree[N] 3:in_degree[N]
//   4:hop_attention[K] 5:Theta[64,64] 6:theta_out[K,64,64] 7:theta_in[K,64,64]
//   8:edge_index[K,2,E] (int32)   output: float32 [N,64]
// ---------------------------------------------------------------------------
extern "C" void kernel_launch(void* const* d_in, const int* in_sizes, int n_in,
                              void* d_out, int out_size) {
    const float* H         = (const float*)d_in[0];
    const float* edge_vals = (const float*)d_in[1];
    const float* out_deg   = (const float*)d_in[2];
    const float* in_deg    = (const float*)d_in[3];
    const float* hop       = (const float*)d_in[4];
    const float* Theta     = (const float*)d_in[5];
    const float* theta_out = (const float*)d_in[6];
    const float* theta_in  = (const float*)d_in[7];
    const int*   edge_idx  = (const int*)d_in[8];

    const int K = in_sizes[4];
    const int N = in_sizes[0] / DD;
    const int E = in_sizes[1] / K;

    alpha_kernel<<<1, 32>>>(hop, K);

    // xgen needs 80KB dynamic smem
    cudaFuncSetAttribute(xgen_kernel, cudaFuncAttributeMaxDynamicSharedMemorySize, 81920);
    int xblocks = (N + 31) / 32;
    xgen_kernel<<<xblocks, 256, 81920>>>(H, out_deg, in_deg, theta_out, theta_in, N, K);

    // One scatter kernel per hop keeps each hop's working set (X_out_k + X_in_k
    // + Sum ~= 77MB) L2-resident.
    for (int k = 0; k < K && k < K_MAX; k++) {
        const int* rows = edge_idx + (size_t)k * 2 * E;
        const int* cols = rows + E;
        const float* vals = edge_vals + (size_t)k * E;
        long long threads = (long long)E * 16;
        int blocks = (int)((threads + 255) / 256);
        scatter_kernel<<<blocks, 256>>>(rows, cols, vals, k, E);
    }

    final_kernel<<<(N + 31) / 32, 256>>>(H, Theta, (float*)d_out, N);
}